// round 2
// baseline (speedup 1.0000x reference)
#include <cuda_runtime.h>
#include <cuda_fp16.h>
#include <mma.h>

using namespace nvcuda;

// Problem constants
#define BB   2
#define SS   2048
#define DD   1024
#define HH   16
#define DHH  64
#define MM   (BB*SS)          // 4096
#define DHID 512              // mech hidden

// ---------------- scratch (device globals; no allocation allowed) -------------
__device__ __half g_xh  [MM*DD];
__device__ __half g_Wqh [DD*DD];
__device__ __half g_Wkh [DD*DD];
__device__ __half g_Wvh [DD*DD];
__device__ __half g_Woh [DD*DD];
__device__ __half g_Wm1h[DHID*DD];
__device__ __half g_Qh  [MM*DD];   // [b*H+h][S][64]
__device__ __half g_Kh  [MM*DD];
__device__ __half g_Vh  [MM*DD];
__device__ __half g_ctxh[MM*DD];   // [b][s][h*64+d]
__device__ float  g_hmid[MM*DHID];
__device__ float  g_logits[MM];
__device__ float  g_mech[MM];

// ---------------- fp32 -> fp16 convert ---------------------------------------
__global__ void f2h_kernel(const float* __restrict__ in, __half* __restrict__ out, int n) {
    int i = blockIdx.x * blockDim.x + threadIdx.x;
    if (i < n) out[i] = __float2half(in[i]);
}

// ---------------- generic 64x64-tile GEMM: C = A[M,1024] * W[N,1024]^T + b ----
// mode 0: QKV (blockIdx.z selects W/bias/dst; Q scaled by 1/8; half out, head-split layout)
// mode 1: fp32 out (row major) -> outF          (output projection)
// mode 2: exact GELU epilogue -> g_hmid (fp32)  (mech layer 1, N=512)
__global__ void __launch_bounds__(256) gemm_kernel(
    const __half* __restrict__ A,
    const __half* __restrict__ Wa, const __half* __restrict__ Wb, const __half* __restrict__ Wc,
    const float*  __restrict__ ba, const float*  __restrict__ bb, const float*  __restrict__ bc,
    float* __restrict__ outF, int mode)
{
    __shared__ __align__(16) __half sAW[2*64*72];
    __half* As = sAW;
    __half* Ws = sAW + 64*72;
    float*  Cs = (float*)sAW;          // reused after compute (64x68 floats <= 2*64*72 halves)

    const __half* Wp = Wa;
    const float*  bp = ba;
    __half* dstH = 0;
    float scale = 1.f;
    if (mode == 0) {
        int z = blockIdx.z;
        Wp   = (z==0) ? Wa : (z==1) ? Wb : Wc;
        bp   = (z==0) ? ba : (z==1) ? bb : bc;
        dstH = (z==0) ? g_Qh : (z==1) ? g_Kh : g_Vh;
        scale = (z==0) ? 0.125f : 1.f;
    }

    const int m0 = blockIdx.x * 64;
    const int n0 = blockIdx.y * 64;
    const int tid = threadIdx.x;
    const int wid = tid >> 5;
    const int wm  = wid & 3;            // m sub-tile
    const int wn  = (wid >> 2) * 2;     // n sub-tiles wn, wn+1

    wmma::fragment<wmma::accumulator,16,16,16,float> acc[2];
    wmma::fill_fragment(acc[0], 0.f);
    wmma::fill_fragment(acc[1], 0.f);

    for (int kt = 0; kt < 16; ++kt) {
        const int k0 = kt * 64;
        // 64 rows x 64 halves = 64 rows x 8 uint4; 512 uint4 per tile, 2 per thread
        #pragma unroll
        for (int i = 0; i < 2; ++i) {
            int idx = tid + i*256;            // 0..511
            int r   = idx >> 3;               // 0..63
            int c8  = idx & 7;                // 0..7 (uint4 = 8 halves)
            *(uint4*)(As + r*72 + c8*8) = *(const uint4*)(A  + (size_t)(m0+r)*1024 + k0 + c8*8);
            *(uint4*)(Ws + r*72 + c8*8) = *(const uint4*)(Wp + (size_t)(n0+r)*1024 + k0 + c8*8);
        }
        __syncthreads();
        #pragma unroll
        for (int kk = 0; kk < 4; ++kk) {
            wmma::fragment<wmma::matrix_a,16,16,16,__half,wmma::row_major> af;
            wmma::load_matrix_sync(af, As + wm*16*72 + kk*16, 72);
            #pragma unroll
            for (int j = 0; j < 2; ++j) {
                wmma::fragment<wmma::matrix_b,16,16,16,__half,wmma::col_major> bf;
                wmma::load_matrix_sync(bf, Ws + (wn+j)*16*72 + kk*16, 72);
                wmma::mma_sync(acc[j], af, bf, acc[j]);
            }
        }
        __syncthreads();
    }

    #pragma unroll
    for (int j = 0; j < 2; ++j)
        wmma::store_matrix_sync(Cs + wm*16*68 + (wn+j)*16, acc[j], 68, wmma::mem_row_major);
    __syncthreads();

    const int row = tid >> 2;
    const int c0  = (tid & 3) * 16;
    const int m   = m0 + row;
    #pragma unroll
    for (int c = 0; c < 16; ++c) {
        int n = n0 + c0 + c;
        float v = Cs[row*68 + c0 + c] + bp[n];
        if (mode == 0) {
            v *= scale;
            int b = m >> 11;     // /2048
            int s = m & 2047;
            int h = n >> 6;
            int d = n & 63;
            dstH[(((size_t)(b*HH + h))*SS + s)*DHH + d] = __float2half(v);
        } else if (mode == 1) {
            outF[(size_t)m*DD + n] = v;
        } else {
            // exact GELU: 0.5*x*(1+erf(x/sqrt(2)))
            float g = 0.5f * v * (1.f + erff(v * 0.70710678118654752f));
            g_hmid[(size_t)m*DHID + n] = g;
        }
    }
}

// ---------------- mech logits: dot(hmid_row, Wm2) + bm2 -----------------------
__global__ void logits_kernel(const float* __restrict__ Wm2, const float* __restrict__ bm2) {
    int m = blockIdx.x;
    int tid = threadIdx.x;           // 128
    float s = 0.f;
    for (int j = tid; j < DHID; j += 128)
        s += g_hmid[(size_t)m*DHID + j] * Wm2[j];
    #pragma unroll
    for (int o = 16; o > 0; o >>= 1) s += __shfl_xor_sync(0xffffffffu, s, o);
    __shared__ float ws[4];
    if ((tid & 31) == 0) ws[tid >> 5] = s;
    __syncthreads();
    if (tid == 0)
        g_logits[m] = ws[0] + ws[1] + ws[2] + ws[3] + bm2[0];
}

// ---------------- per-batch softmax over S=2048 -------------------------------
__global__ void mech_softmax_kernel(float* __restrict__ out_tail) {
    int b = blockIdx.x;
    int tid = threadIdx.x;           // 256
    __shared__ float red[256];
    float mx = -1e30f;
    for (int i = tid; i < SS; i += 256) mx = fmaxf(mx, g_logits[b*SS + i]);
    red[tid] = mx; __syncthreads();
    for (int s = 128; s > 0; s >>= 1) { if (tid < s) red[tid] = fmaxf(red[tid], red[tid+s]); __syncthreads(); }
    mx = red[0]; __syncthreads();
    float sm = 0.f;
    for (int i = tid; i < SS; i += 256) sm += __expf(g_logits[b*SS + i] - mx);
    red[tid] = sm; __syncthreads();
    for (int s = 128; s > 0; s >>= 1) { if (tid < s) red[tid] += red[tid+s]; __syncthreads(); }
    float inv = 1.f / red[0];
    for (int i = tid; i < SS; i += 256) {
        float v = __expf(g_logits[b*SS + i] - mx) * inv;
        g_mech[b*SS + i] = v;
        out_tail[b*SS + i] = v;
    }
}

// ---------------- single-pass attention (no running max; scores are bounded) --
// block: 64 queries for one (b,h); loops 32 key-tiles of 64.
__global__ void __launch_bounds__(256) attn_kernel(const int* __restrict__ mask) {
    __shared__ __align__(16) __half Qs [64*72];
    __shared__ __align__(16) __half KPs[64*72];   // K tile, then reused for P tile
    __shared__ __align__(16) __half Vs [64*72];
    __shared__ __align__(16) float  Ssm[64*68];
    __shared__ float l_s[64];
    __shared__ float bias_s[64];

    const int q0  = blockIdx.x * 64;
    const int bh  = blockIdx.y;
    const int b   = bh >> 4;
    const int h   = bh & 15;
    const int tid = threadIdx.x;
    const int wid = tid >> 5;
    const int wm  = wid & 3;
    const int wn  = (wid >> 2) * 2;

    const __half* Qg = g_Qh + (size_t)bh * SS * DHH;
    const __half* Kg = g_Kh + (size_t)bh * SS * DHH;
    const __half* Vg = g_Vh + (size_t)bh * SS * DHH;

    // Q tile: 64 rows x 64 halves = 512 uint4; 2 per thread
    #pragma unroll
    for (int i = 0; i < 2; ++i) {
        int idx = tid + i*256;      // 0..511
        int r = idx >> 3, c8 = idx & 7;
        *(uint4*)(Qs + r*72 + c8*8) = *(const uint4*)(Qg + (size_t)(q0+r)*DHH + c8*8);
    }
    if (tid < 64) l_s[tid] = 0.f;

    wmma::fragment<wmma::accumulator,16,16,16,float> oacc[2];
    wmma::fill_fragment(oacc[0], 0.f);
    wmma::fill_fragment(oacc[1], 0.f);

    for (int kt = 0; kt < 32; ++kt) {
        const int k0 = kt * 64;
        #pragma unroll
        for (int i = 0; i < 2; ++i) {
            int idx = tid + i*256;
            int r = idx >> 3, c8 = idx & 7;
            *(uint4*)(KPs + r*72 + c8*8) = *(const uint4*)(Kg + (size_t)(k0+r)*DHH + c8*8);
            *(uint4*)(Vs  + r*72 + c8*8) = *(const uint4*)(Vg + (size_t)(k0+r)*DHH + c8*8);
        }
        if (tid < 64) {
            int key = k0 + tid;
            int mv  = mask[b*SS + key];
            bias_s[tid] = mv ? 2.0f * g_mech[b*SS + key] : -1e30f;
        }
        __syncthreads();

        // S = Q * K^T  (64x64, k-dim = 64)
        wmma::fragment<wmma::accumulator,16,16,16,float> sacc[2];
        wmma::fill_fragment(sacc[0], 0.f);
        wmma::fill_fragment(sacc[1], 0.f);
        #pragma unroll
        for (int kk = 0; kk < 4; ++kk) {
            wmma::fragment<wmma::matrix_a,16,16,16,__half,wmma::row_major> af;
            wmma::load_matrix_sync(af, Qs + wm*16*72 + kk*16, 72);
            #pragma unroll
            for (int j = 0; j < 2; ++j) {
                wmma::fragment<wmma::matrix_b,16,16,16,__half,wmma::col_major> bf;
                wmma::load_matrix_sync(bf, KPs + (wn+j)*16*72 + kk*16, 72);
                wmma::mma_sync(sacc[j], af, bf, sacc[j]);
            }
        }
        #pragma unroll
        for (int j = 0; j < 2; ++j)
            wmma::store_matrix_sync(Ssm + wm*16*68 + (wn+j)*16, sacc[j], 68, wmma::mem_row_major);
        __syncthreads();

        // P = exp(S + bias); rowsum into l_s; P (half) overwrites K tile
        {
            const int row = tid >> 2;
            const int c0  = (tid & 3) * 16;
            float rs = 0.f;
            #pragma unroll
            for (int c = 0; c < 16; ++c) {
                float sv = Ssm[row*68 + c0 + c] + bias_s[c0 + c];
                float p  = __expf(sv);
                rs += p;
                KPs[row*72 + c0 + c] = __float2half(p);
            }
            rs += __shfl_xor_sync(0xffffffffu, rs, 1);
            rs += __shfl_xor_sync(0xffffffffu, rs, 2);
            if ((tid & 3) == 0) l_s[row] += rs;
        }
        __syncthreads();

        // O += P * V
        #pragma unroll
        for (int kk = 0; kk < 4; ++kk) {
            wmma::fragment<wmma::matrix_a,16,16,16,__half,wmma::row_major> af;
            wmma::load_matrix_sync(af, KPs + wm*16*72 + kk*16, 72);
            #pragma unroll
            for (int j = 0; j < 2; ++j) {
                wmma::fragment<wmma::matrix_b,16,16,16,__half,wmma::row_major> bf;
                wmma::load_matrix_sync(bf, Vs + kk*16*72 + (wn+j)*16, 72);
                wmma::mma_sync(oacc[j], af, bf, oacc[j]);
            }
        }
        __syncthreads();
    }

    #pragma unroll
    for (int j = 0; j < 2; ++j)
        wmma::store_matrix_sync(Ssm + wm*16*68 + (wn+j)*16, oacc[j], 68, wmma::mem_row_major);
    __syncthreads();
    {
        const int row = tid >> 2;
        const int c0  = (tid & 3) * 16;
        const int q   = q0 + row;
        float inv = 1.f / l_s[row];
        #pragma unroll
        for (int c = 0; c < 16; ++c) {
            float o = Ssm[row*68 + c0 + c] * inv;
            g_ctxh[((size_t)(b*SS + q))*DD + h*DHH + c0 + c] = __float2half(o);
        }
    }
}

// ---------------- host launcher ----------------------------------------------
static void* symaddr(const void* sym) { void* p = 0; cudaGetSymbolAddress(&p, sym); return p; }

extern "C" void kernel_launch(void* const* d_in, const int* in_sizes, int n_in,
                              void* d_out, int out_size) {
    const float* x   = (const float*)d_in[0];
    const int*   mask= (const int*)  d_in[1];
    const float* Wq  = (const float*)d_in[2];
    const float* bq  = (const float*)d_in[3];
    const float* Wk  = (const float*)d_in[4];
    const float* bk  = (const float*)d_in[5];
    const float* Wv  = (const float*)d_in[6];
    const float* bv  = (const float*)d_in[7];
    const float* Wo  = (const float*)d_in[8];
    const float* bo  = (const float*)d_in[9];
    const float* Wm1 = (const float*)d_in[10];
    const float* bm1 = (const float*)d_in[11];
    const float* Wm2 = (const float*)d_in[12];
    const float* bm2 = (const float*)d_in[13];
    float* out = (float*)d_out;

    __half* xh   = (__half*)symaddr(g_xh);
    __half* Wqh  = (__half*)symaddr(g_Wqh);
    __half* Wkh  = (__half*)symaddr(g_Wkh);
    __half* Wvh  = (__half*)symaddr(g_Wvh);
    __half* Woh  = (__half*)symaddr(g_Woh);
    __half* Wm1h = (__half*)symaddr(g_Wm1h);
    __half* ctxh = (__half*)symaddr(g_ctxh);

    // 1. convert inputs to fp16
    f2h_kernel<<<(MM*DD + 255)/256, 256>>>(x,   xh,   MM*DD);
    f2h_kernel<<<(DD*DD + 255)/256, 256>>>(Wq,  Wqh,  DD*DD);
    f2h_kernel<<<(DD*DD + 255)/256, 256>>>(Wk,  Wkh,  DD*DD);
    f2h_kernel<<<(DD*DD + 255)/256, 256>>>(Wv,  Wvh,  DD*DD);
    f2h_kernel<<<(DD*DD + 255)/256, 256>>>(Wo,  Woh,  DD*DD);
    f2h_kernel<<<(DHID*DD + 255)/256, 256>>>(Wm1, Wm1h, DHID*DD);

    // 2. fused QKV projections (Q scaled by 1/sqrt(64))
    gemm_kernel<<<dim3(MM/64, DD/64, 3), 256>>>(xh, Wqh, Wkh, Wvh, bq, bk, bv, 0, 0);

    // 3. mechanism MLP layer 1 (+GELU)
    gemm_kernel<<<dim3(MM/64, DHID/64, 1), 256>>>(xh, Wm1h, Wm1h, Wm1h, bm1, bm1, bm1, 0, 2);

    // 4. mechanism logits + softmax (-> mech strengths, also second output)
    logits_kernel<<<MM, 128>>>(Wm2, bm2);
    mech_softmax_kernel<<<BB, 256>>>(out + (size_t)MM*DD);

    // 5. attention
    attn_kernel<<<dim3(SS/64, BB*HH), 256>>>(mask);

    // 6. output projection -> d_out
    gemm_kernel<<<dim3(MM/64, DD/64, 1), 256>>>((const __half*)ctxh, Woh, Woh, Woh, bo, bo, bo, out, 1);
}

// round 3
// speedup vs baseline: 1.5031x; 1.5031x over previous
#include <cuda_runtime.h>
#include <cuda_fp16.h>
#include <mma.h>

using namespace nvcuda;

// Problem constants
#define BB   2
#define SS   2048
#define DD   1024
#define HH   16
#define DHH  64
#define MM   (BB*SS)          // 4096
#define DHID 512              // mech hidden

// ---------------- scratch (device globals; no allocation allowed) -------------
__device__ __half g_xh  [MM*DD];
__device__ __half g_Wqh [DD*DD];
__device__ __half g_Wkh [DD*DD];
__device__ __half g_Wvh [DD*DD];
__device__ __half g_Woh [DD*DD];
__device__ __half g_Wm1h[DHID*DD];
__device__ __half g_Qh  [MM*DD];   // [b*H+h][S][64]
__device__ __half g_Kh  [MM*DD];
__device__ __half g_Vh  [MM*DD];
__device__ __half g_ctxh[MM*DD];   // [b][s][h*64+d]
__device__ float  g_hmid[MM*DHID];
__device__ float  g_logits[MM];
__device__ float  g_mech[MM];

// ---------------- cp.async helpers -------------------------------------------
__device__ __forceinline__ void cp16(void* s, const void* g) {
    asm volatile("cp.async.ca.shared.global [%0], [%1], 16;"
                 :: "r"((unsigned)__cvta_generic_to_shared(s)), "l"(g));
}
#define CP_COMMIT() asm volatile("cp.async.commit_group;")
#define CP_WAIT0()  asm volatile("cp.async.wait_group 0;")

// ---------------- fp32 -> fp16 convert (vectorized) ---------------------------
__global__ void f2h_kernel(const float4* __restrict__ in, uint2* __restrict__ out, int n4) {
    int i = blockIdx.x * blockDim.x + threadIdx.x;
    if (i < n4) {
        float4 v = in[i];
        __half2 h0 = __floats2half2_rn(v.x, v.y);
        __half2 h1 = __floats2half2_rn(v.z, v.w);
        out[i] = make_uint2(*(unsigned*)&h0, *(unsigned*)&h1);
    }
}

// ---------------- 128x128-tile GEMM: C = A[M,1024] * W[N,1024]^T + b ----------
// mode 0: QKV (blockIdx.z selects W/bias/dst; Q scaled by 1/8; half out, head-split)
// mode 1: fp32 out (row major) -> outF
// mode 2: exact GELU epilogue -> g_hmid (fp32)
// dynamic smem: 2 stages x (128x72 A + 128x72 B) halves = 73728 B; epilogue Cs 128x132 f32
__global__ void __launch_bounds__(256) gemm_kernel(
    const __half* __restrict__ A,
    const __half* __restrict__ Wa, const __half* __restrict__ Wb, const __half* __restrict__ Wc,
    const float*  __restrict__ ba, const float*  __restrict__ bb, const float*  __restrict__ bc,
    float* __restrict__ outF, int mode)
{
    extern __shared__ __align__(16) char dyn[];
    __half* As = (__half*)dyn;           // 2 * 128*72
    __half* Bs = As + 2*128*72;          // 2 * 128*72
    float*  Cs = (float*)dyn;            // reuse: 128*132 floats = 67584B <= 73728B

    const __half* Wp = Wa;
    const float*  bp = ba;
    __half* dstH = 0;
    float scale = 1.f;
    if (mode == 0) {
        int z = blockIdx.z;
        Wp   = (z==0) ? Wa : (z==1) ? Wb : Wc;
        bp   = (z==0) ? ba : (z==1) ? bb : bc;
        dstH = (z==0) ? g_Qh : (z==1) ? g_Kh : g_Vh;
        scale = (z==0) ? 0.125f : 1.f;
    }

    const int m0 = blockIdx.x * 128;
    const int n0 = blockIdx.y * 128;
    const int tid = threadIdx.x;
    const int wid = tid >> 5;
    const int wr  = wid & 1;       // m: 2 x 64
    const int wc  = wid >> 1;      // n: 4 x 32

    wmma::fragment<wmma::accumulator,16,16,16,float> acc[4][2];
    #pragma unroll
    for (int i = 0; i < 4; ++i) { wmma::fill_fragment(acc[i][0], 0.f); wmma::fill_fragment(acc[i][1], 0.f); }

    // stage loader: 128 rows x 8 16B-chunks each for A and B
    #define GEMM_LOAD(kt, st) do {                                                  \
        const int k0_ = (kt)*64;                                                    \
        __half* as_ = As + (st)*128*72;                                             \
        __half* bs_ = Bs + (st)*128*72;                                             \
        _Pragma("unroll")                                                           \
        for (int i_ = 0; i_ < 4; ++i_) {                                            \
            int idx_ = tid + i_*256;                                                \
            int r_ = idx_ >> 3, c8_ = idx_ & 7;                                     \
            cp16(as_ + r_*72 + c8_*8, A  + (size_t)(m0+r_)*1024 + k0_ + c8_*8);     \
            cp16(bs_ + r_*72 + c8_*8, Wp + (size_t)(n0+r_)*1024 + k0_ + c8_*8);     \
        }                                                                           \
    } while(0)

    GEMM_LOAD(0, 0); CP_COMMIT();

    for (int kt = 0; kt < 16; ++kt) {
        CP_WAIT0();
        __syncthreads();
        if (kt < 15) { GEMM_LOAD(kt+1, (kt+1)&1); CP_COMMIT(); }
        const __half* as = As + (kt&1)*128*72;
        const __half* bs = Bs + (kt&1)*128*72;
        #pragma unroll
        for (int kk = 0; kk < 4; ++kk) {
            wmma::fragment<wmma::matrix_a,16,16,16,__half,wmma::row_major> af[4];
            #pragma unroll
            for (int fm = 0; fm < 4; ++fm)
                wmma::load_matrix_sync(af[fm], as + (wr*64 + fm*16)*72 + kk*16, 72);
            #pragma unroll
            for (int fn = 0; fn < 2; ++fn) {
                wmma::fragment<wmma::matrix_b,16,16,16,__half,wmma::col_major> bf;
                wmma::load_matrix_sync(bf, bs + (wc*32 + fn*16)*72 + kk*16, 72);
                #pragma unroll
                for (int fm = 0; fm < 4; ++fm)
                    wmma::mma_sync(acc[fm][fn], af[fm], bf, acc[fm][fn]);
            }
        }
    }
    __syncthreads();   // done with As/Bs; Cs aliases them

    #pragma unroll
    for (int fm = 0; fm < 4; ++fm)
        #pragma unroll
        for (int fn = 0; fn < 2; ++fn)
            wmma::store_matrix_sync(Cs + (wr*64 + fm*16)*132 + wc*32 + fn*16, acc[fm][fn], 132, wmma::mem_row_major);
    __syncthreads();

    // epilogue: thread -> row = tid>>1 (0..127), col base = (tid&1)*64
    const int row = tid >> 1;
    const int cb  = (tid & 1) * 64;
    const int m   = m0 + row;
    if (mode == 0) {
        int b = m >> 11, s = m & 2047;
        int h = (n0 + cb) >> 6;                 // fixed within 64-col span
        __half* dst = dstH + (((size_t)(b*HH + h))*SS + s)*DHH;
        #pragma unroll
        for (int c0 = 0; c0 < 64; c0 += 8) {
            __half hv[8];
            #pragma unroll
            for (int e = 0; e < 8; ++e)
                hv[e] = __float2half((Cs[row*132 + cb + c0 + e] + bp[n0 + cb + c0 + e]) * scale);
            *(uint4*)&dst[c0] = *(uint4*)hv;
        }
    } else if (mode == 1) {
        float* dst = outF + (size_t)m*DD + n0 + cb;
        #pragma unroll
        for (int c = 0; c < 64; ++c)
            dst[c] = Cs[row*132 + cb + c] + bp[n0 + cb + c];
    } else {
        float* dst = g_hmid + (size_t)m*DHID + n0 + cb;
        #pragma unroll
        for (int c = 0; c < 64; ++c) {
            float v = Cs[row*132 + cb + c] + bp[n0 + cb + c];
            dst[c] = 0.5f * v * (1.f + erff(v * 0.70710678118654752f));
        }
    }
}

// ---------------- mech logits: dot(hmid_row, Wm2) + bm2 -----------------------
__global__ void logits_kernel(const float* __restrict__ Wm2, const float* __restrict__ bm2) {
    int m = blockIdx.x;
    int tid = threadIdx.x;           // 128
    float s = 0.f;
    for (int j = tid; j < DHID; j += 128)
        s += g_hmid[(size_t)m*DHID + j] * Wm2[j];
    #pragma unroll
    for (int o = 16; o > 0; o >>= 1) s += __shfl_xor_sync(0xffffffffu, s, o);
    __shared__ float ws[4];
    if ((tid & 31) == 0) ws[tid >> 5] = s;
    __syncthreads();
    if (tid == 0)
        g_logits[m] = ws[0] + ws[1] + ws[2] + ws[3] + bm2[0];
}

// ---------------- per-batch softmax over S=2048 -------------------------------
__global__ void mech_softmax_kernel(float* __restrict__ out_tail) {
    int b = blockIdx.x;
    int tid = threadIdx.x;           // 256
    __shared__ float red[256];
    float mx = -1e30f;
    for (int i = tid; i < SS; i += 256) mx = fmaxf(mx, g_logits[b*SS + i]);
    red[tid] = mx; __syncthreads();
    for (int s = 128; s > 0; s >>= 1) { if (tid < s) red[tid] = fmaxf(red[tid], red[tid+s]); __syncthreads(); }
    mx = red[0]; __syncthreads();
    float sm = 0.f;
    for (int i = tid; i < SS; i += 256) sm += __expf(g_logits[b*SS + i] - mx);
    red[tid] = sm; __syncthreads();
    for (int s = 128; s > 0; s >>= 1) { if (tid < s) red[tid] += red[tid+s]; __syncthreads(); }
    float inv = 1.f / red[0];
    for (int i = tid; i < SS; i += 256) {
        float v = __expf(g_logits[b*SS + i] - mx) * inv;
        g_mech[b*SS + i] = v;
        out_tail[b*SS + i] = v;
    }
}

// ---------------- attention: 128 queries/block, double-buffered K/V -----------
// warp w owns q rows [w*16, w*16+16); scores bounded -> unnormalized exp is safe.
// dynamic smem: Qs 128x72h | K 2x64x72h | V 2x64x72h | P 128x72h | wbuf 8x16x20f | bias 2048f
__global__ void __launch_bounds__(256) attn_kernel(const int* __restrict__ mask) {
    extern __shared__ __align__(16) char dyn[];
    __half* Qs  = (__half*)dyn;              // 128*72
    __half* Ks  = Qs + 128*72;               // 2*64*72
    __half* Vs  = Ks + 2*64*72;              // 2*64*72
    __half* Ps  = Vs + 2*64*72;              // 128*72 (warp-private 16-row slices)
    float*  wbuf= (float*)(Ps + 128*72);     // 8*16*20 floats
    float*  bias= wbuf + 8*16*20;            // 2048 floats

    const int q0  = blockIdx.x * 128;
    const int bh  = blockIdx.y;
    const int b   = bh >> 4;
    const int h   = bh & 15;
    const int tid = threadIdx.x;
    const int w   = tid >> 5;
    const int lane= tid & 31;
    const int rrow= lane >> 1;         // 0..15: this lane's row within warp tile
    const int cb  = (lane & 1) * 8;    // col offset within 16-col fragment

    const __half* Qg = g_Qh + (size_t)bh * SS * DHH;
    const __half* Kg = g_Kh + (size_t)bh * SS * DHH;
    const __half* Vg = g_Vh + (size_t)bh * SS * DHH;

    // Q tile: 128 rows x 8 chunks
    #pragma unroll
    for (int i = 0; i < 4; ++i) {
        int idx = tid + i*256;     // 0..1023
        int r = idx >> 3, c8 = idx & 7;
        cp16(Qs + r*72 + c8*8, Qg + (size_t)(q0+r)*DHH + c8*8);
    }
    // bias vector for all 2048 keys (once per block)
    for (int i = tid; i < SS; i += 256)
        bias[i] = mask[b*SS + i] ? 2.0f * g_mech[b*SS + i] : -1e30f;

    #define KV_LOAD(kt, st) do {                                                  \
        const int k0_ = (kt)*64;                                                  \
        __half* ks_ = Ks + (st)*64*72;                                            \
        __half* vs_ = Vs + (st)*64*72;                                            \
        _Pragma("unroll")                                                         \
        for (int i_ = 0; i_ < 2; ++i_) {                                          \
            int idx_ = tid + i_*256;                                              \
            int r_ = idx_ >> 3, c8_ = idx_ & 7;                                   \
            cp16(ks_ + r_*72 + c8_*8, Kg + (size_t)(k0_+r_)*DHH + c8_*8);         \
            cp16(vs_ + r_*72 + c8_*8, Vg + (size_t)(k0_+r_)*DHH + c8_*8);         \
        }                                                                         \
    } while(0)

    KV_LOAD(0, 0); CP_COMMIT();

    wmma::fragment<wmma::accumulator,16,16,16,float> oacc[4];
    #pragma unroll
    for (int j = 0; j < 4; ++j) wmma::fill_fragment(oacc[j], 0.f);
    float rs = 0.f;                    // unnormalized row sum for row (w*16+rrow)
    float* wb = wbuf + w*16*20;

    for (int kt = 0; kt < 32; ++kt) {
        CP_WAIT0();
        __syncthreads();
        if (kt < 31) { KV_LOAD(kt+1, (kt+1)&1); CP_COMMIT(); }
        const __half* ks = Ks + (kt&1)*64*72;
        const __half* vs = Vs + (kt&1)*64*72;
        const int k0 = kt*64;

        // S = Q K^T : warp computes 16x64
        wmma::fragment<wmma::accumulator,16,16,16,float> sacc[4];
        #pragma unroll
        for (int j = 0; j < 4; ++j) wmma::fill_fragment(sacc[j], 0.f);
        #pragma unroll
        for (int kk = 0; kk < 4; ++kk) {
            wmma::fragment<wmma::matrix_a,16,16,16,__half,wmma::row_major> af;
            wmma::load_matrix_sync(af, Qs + (w*16)*72 + kk*16, 72);
            #pragma unroll
            for (int nf = 0; nf < 4; ++nf) {
                wmma::fragment<wmma::matrix_b,16,16,16,__half,wmma::col_major> bf;
                wmma::load_matrix_sync(bf, ks + (nf*16)*72 + kk*16, 72);
                wmma::mma_sync(sacc[nf], af, bf, sacc[nf]);
            }
        }

        // exp + bias, warp-private (no block barrier)
        #pragma unroll
        for (int nf = 0; nf < 4; ++nf) {
            wmma::store_matrix_sync(wb, sacc[nf], 20, wmma::mem_row_major);
            __syncwarp();
            __half hv[8];
            #pragma unroll
            for (int e = 0; e < 8; ++e) {
                float sv = wb[rrow*20 + cb + e] + bias[k0 + nf*16 + cb + e];
                float p = __expf(sv);
                rs += p;
                hv[e] = __float2half(p);
            }
            *(uint4*)&Ps[(w*16 + rrow)*72 + nf*16 + cb] = *(uint4*)hv;
            __syncwarp();
        }

        // O += P V
        #pragma unroll
        for (int kk = 0; kk < 4; ++kk) {
            wmma::fragment<wmma::matrix_a,16,16,16,__half,wmma::row_major> af;
            wmma::load_matrix_sync(af, Ps + (w*16)*72 + kk*16, 72);
            #pragma unroll
            for (int nf = 0; nf < 4; ++nf) {
                wmma::fragment<wmma::matrix_b,16,16,16,__half,wmma::row_major> bf;
                wmma::load_matrix_sync(bf, vs + (kk*16)*72 + nf*16, 72);
                wmma::mma_sync(oacc[nf], af, bf, oacc[nf]);
            }
        }
    }

    // epilogue: normalize and write ctx
    rs += __shfl_xor_sync(0xffffffffu, rs, 1);    // both lanes of a row pair get total
    float inv = 1.f / rs;
    __half* dst = g_ctxh + ((size_t)(b*SS + q0 + w*16 + rrow))*DD + h*DHH;
    #pragma unroll
    for (int nf = 0; nf < 4; ++nf) {
        __syncwarp();
        wmma::store_matrix_sync(wb, oacc[nf], 20, wmma::mem_row_major);
        __syncwarp();
        __half hv[8];
        #pragma unroll
        for (int e = 0; e < 8; ++e)
            hv[e] = __float2half(wb[rrow*20 + cb + e] * inv);
        *(uint4*)&dst[nf*16 + cb] = *(uint4*)hv;
    }
}

// ---------------- host launcher ----------------------------------------------
static void* symaddr(const void* sym) { void* p = 0; cudaGetSymbolAddress(&p, sym); return p; }

#define GEMM_SMEM 73728
#define ATTN_SMEM 92160

extern "C" void kernel_launch(void* const* d_in, const int* in_sizes, int n_in,
                              void* d_out, int out_size) {
    const float* x   = (const float*)d_in[0];
    const int*   mask= (const int*)  d_in[1];
    const float* Wq  = (const float*)d_in[2];
    const float* bq  = (const float*)d_in[3];
    const float* Wk  = (const float*)d_in[4];
    const float* bk  = (const float*)d_in[5];
    const float* Wv  = (const float*)d_in[6];
    const float* bv  = (const float*)d_in[7];
    const float* Wo  = (const float*)d_in[8];
    const float* bo  = (const float*)d_in[9];
    const float* Wm1 = (const float*)d_in[10];
    const float* bm1 = (const float*)d_in[11];
    const float* Wm2 = (const float*)d_in[12];
    const float* bm2 = (const float*)d_in[13];
    float* out = (float*)d_out;

    __half* xh   = (__half*)symaddr(g_xh);
    __half* Wqh  = (__half*)symaddr(g_Wqh);
    __half* Wkh  = (__half*)symaddr(g_Wkh);
    __half* Wvh  = (__half*)symaddr(g_Wvh);
    __half* Woh  = (__half*)symaddr(g_Woh);
    __half* Wm1h = (__half*)symaddr(g_Wm1h);
    __half* ctxh = (__half*)symaddr(g_ctxh);

    cudaFuncSetAttribute(gemm_kernel, cudaFuncAttributeMaxDynamicSharedMemorySize, GEMM_SMEM);
    cudaFuncSetAttribute(attn_kernel, cudaFuncAttributeMaxDynamicSharedMemorySize, ATTN_SMEM);

    // 1. convert inputs to fp16 (vectorized: n always /4)
    f2h_kernel<<<(MM*DD/4 + 255)/256, 256>>>((const float4*)x,   (uint2*)xh,   MM*DD/4);
    f2h_kernel<<<(DD*DD/4 + 255)/256, 256>>>((const float4*)Wq,  (uint2*)Wqh,  DD*DD/4);
    f2h_kernel<<<(DD*DD/4 + 255)/256, 256>>>((const float4*)Wk,  (uint2*)Wkh,  DD*DD/4);
    f2h_kernel<<<(DD*DD/4 + 255)/256, 256>>>((const float4*)Wv,  (uint2*)Wvh,  DD*DD/4);
    f2h_kernel<<<(DD*DD/4 + 255)/256, 256>>>((const float4*)Wo,  (uint2*)Woh,  DD*DD/4);
    f2h_kernel<<<(DHID*DD/4 + 255)/256, 256>>>((const float4*)Wm1, (uint2*)Wm1h, DHID*DD/4);

    // 2. fused QKV projections (Q scaled by 1/sqrt(64))
    gemm_kernel<<<dim3(MM/128, DD/128, 3), 256, GEMM_SMEM>>>(xh, Wqh, Wkh, Wvh, bq, bk, bv, 0, 0);

    // 3. mechanism MLP layer 1 (+GELU)
    gemm_kernel<<<dim3(MM/128, DHID/128, 1), 256, GEMM_SMEM>>>(xh, Wm1h, Wm1h, Wm1h, bm1, bm1, bm1, 0, 2);

    // 4. mechanism logits + softmax (-> mech strengths, also second output)
    logits_kernel<<<MM, 128>>>(Wm2, bm2);
    mech_softmax_kernel<<<BB, 256>>>(out + (size_t)MM*DD);

    // 5. attention
    attn_kernel<<<dim3(SS/128, BB*HH), 256, ATTN_SMEM>>>(mask);

    // 6. output projection -> d_out
    gemm_kernel<<<dim3(MM/128, DD/128, 1), 256, GEMM_SMEM>>>((const __half*)ctxh, Woh, Woh, Woh, bo, bo, bo, out, 1);
}

// round 4
// speedup vs baseline: 1.9303x; 1.2842x over previous
#include <cuda_runtime.h>
#include <cuda_fp16.h>
#include <mma.h>
#include <cstdint>

using namespace nvcuda;

// Problem constants
#define BB   2
#define SS   2048
#define DD   1024
#define HH   16
#define DHH  64
#define MM   (BB*SS)          // 4096
#define DHID 512              // mech hidden

// ---------------- scratch (device globals; no allocation allowed) -------------
__device__ __half g_xh  [MM*DD];
__device__ __half g_Wqh [DD*DD];
__device__ __half g_Wkh [DD*DD];
__device__ __half g_Wvh [DD*DD];
__device__ __half g_Woh [DD*DD];
__device__ __half g_Wm1h[DHID*DD];
__device__ __half g_Qh  [MM*DD];   // [b*H+h][S][64]
__device__ __half g_Kh  [MM*DD];
__device__ __half g_Vh  [MM*DD];
__device__ __half g_ctxh[MM*DD];   // [b][s][h*64+d]
__device__ float  g_hmid[MM*DHID];
__device__ float  g_logits[MM];
__device__ float  g_mech[MM];

// ---------------- cp.async helpers -------------------------------------------
__device__ __forceinline__ void cp16(void* s, const void* g) {
    asm volatile("cp.async.ca.shared.global [%0], [%1], 16;"
                 :: "r"((unsigned)__cvta_generic_to_shared(s)), "l"(g));
}
#define CP_COMMIT() asm volatile("cp.async.commit_group;")
#define CP_WAIT0()  asm volatile("cp.async.wait_group 0;")

// ---------------- mma.sync helpers --------------------------------------------
__device__ __forceinline__ void ldm_x4(uint32_t r[4], uint32_t addr) {
    asm volatile("ldmatrix.sync.aligned.m8n8.x4.shared.b16 {%0,%1,%2,%3}, [%4];"
                 : "=r"(r[0]), "=r"(r[1]), "=r"(r[2]), "=r"(r[3]) : "r"(addr));
}
__device__ __forceinline__ void ldm_x4_t(uint32_t r[4], uint32_t addr) {
    asm volatile("ldmatrix.sync.aligned.m8n8.x4.trans.shared.b16 {%0,%1,%2,%3}, [%4];"
                 : "=r"(r[0]), "=r"(r[1]), "=r"(r[2]), "=r"(r[3]) : "r"(addr));
}
__device__ __forceinline__ void mma16816(float c[4], const uint32_t a[4], uint32_t b0, uint32_t b1) {
    asm volatile("mma.sync.aligned.m16n8k16.row.col.f32.f16.f16.f32 "
                 "{%0,%1,%2,%3}, {%4,%5,%6,%7}, {%8,%9}, {%0,%1,%2,%3};"
                 : "+f"(c[0]), "+f"(c[1]), "+f"(c[2]), "+f"(c[3])
                 : "r"(a[0]), "r"(a[1]), "r"(a[2]), "r"(a[3]), "r"(b0), "r"(b1));
}

// ---------------- fp32 -> fp16 convert (vectorized) ---------------------------
__global__ void f2h_kernel(const float4* __restrict__ in, uint2* __restrict__ out, int n4) {
    int i = blockIdx.x * blockDim.x + threadIdx.x;
    if (i < n4) {
        float4 v = in[i];
        __half2 h0 = __floats2half2_rn(v.x, v.y);
        __half2 h1 = __floats2half2_rn(v.z, v.w);
        out[i] = make_uint2(*(unsigned*)&h0, *(unsigned*)&h1);
    }
}

// ---------------- 128x128-tile GEMM: C = A[M,1024] * W[N,1024]^T + b ----------
__global__ void __launch_bounds__(256) gemm_kernel(
    const __half* __restrict__ A,
    const __half* __restrict__ Wa, const __half* __restrict__ Wb, const __half* __restrict__ Wc,
    const float*  __restrict__ ba, const float*  __restrict__ bb, const float*  __restrict__ bc,
    float* __restrict__ outF, int mode)
{
    extern __shared__ __align__(16) char dyn[];
    __half* As = (__half*)dyn;           // 2 * 128*72
    __half* Bs = As + 2*128*72;          // 2 * 128*72
    float*  Cs = (float*)dyn;            // reuse: 128*132 floats

    const __half* Wp = Wa;
    const float*  bp = ba;
    __half* dstH = 0;
    float scale = 1.f;
    if (mode == 0) {
        int z = blockIdx.z;
        Wp   = (z==0) ? Wa : (z==1) ? Wb : Wc;
        bp   = (z==0) ? ba : (z==1) ? bb : bc;
        dstH = (z==0) ? g_Qh : (z==1) ? g_Kh : g_Vh;
        scale = (z==0) ? 0.125f : 1.f;
    }

    const int m0 = blockIdx.x * 128;
    const int n0 = blockIdx.y * 128;
    const int tid = threadIdx.x;
    const int wid = tid >> 5;
    const int wr  = wid & 1;       // m: 2 x 64
    const int wc  = wid >> 1;      // n: 4 x 32

    wmma::fragment<wmma::accumulator,16,16,16,float> acc[4][2];
    #pragma unroll
    for (int i = 0; i < 4; ++i) { wmma::fill_fragment(acc[i][0], 0.f); wmma::fill_fragment(acc[i][1], 0.f); }

    #define GEMM_LOAD(kt, st) do {                                                  \
        const int k0_ = (kt)*64;                                                    \
        __half* as_ = As + (st)*128*72;                                             \
        __half* bs_ = Bs + (st)*128*72;                                             \
        _Pragma("unroll")                                                           \
        for (int i_ = 0; i_ < 4; ++i_) {                                            \
            int idx_ = tid + i_*256;                                                \
            int r_ = idx_ >> 3, c8_ = idx_ & 7;                                     \
            cp16(as_ + r_*72 + c8_*8, A  + (size_t)(m0+r_)*1024 + k0_ + c8_*8);     \
            cp16(bs_ + r_*72 + c8_*8, Wp + (size_t)(n0+r_)*1024 + k0_ + c8_*8);     \
        }                                                                           \
    } while(0)

    GEMM_LOAD(0, 0); CP_COMMIT();

    for (int kt = 0; kt < 16; ++kt) {
        CP_WAIT0();
        __syncthreads();
        if (kt < 15) { GEMM_LOAD(kt+1, (kt+1)&1); CP_COMMIT(); }
        const __half* as = As + (kt&1)*128*72;
        const __half* bs = Bs + (kt&1)*128*72;
        #pragma unroll
        for (int kk = 0; kk < 4; ++kk) {
            wmma::fragment<wmma::matrix_a,16,16,16,__half,wmma::row_major> af[4];
            #pragma unroll
            for (int fm = 0; fm < 4; ++fm)
                wmma::load_matrix_sync(af[fm], as + (wr*64 + fm*16)*72 + kk*16, 72);
            #pragma unroll
            for (int fn = 0; fn < 2; ++fn) {
                wmma::fragment<wmma::matrix_b,16,16,16,__half,wmma::col_major> bf;
                wmma::load_matrix_sync(bf, bs + (wc*32 + fn*16)*72 + kk*16, 72);
                #pragma unroll
                for (int fm = 0; fm < 4; ++fm)
                    wmma::mma_sync(acc[fm][fn], af[fm], bf, acc[fm][fn]);
            }
        }
    }
    __syncthreads();

    #pragma unroll
    for (int fm = 0; fm < 4; ++fm)
        #pragma unroll
        for (int fn = 0; fn < 2; ++fn)
            wmma::store_matrix_sync(Cs + (wr*64 + fm*16)*132 + wc*32 + fn*16, acc[fm][fn], 132, wmma::mem_row_major);
    __syncthreads();

    const int row = tid >> 1;
    const int cb  = (tid & 1) * 64;
    const int m   = m0 + row;
    if (mode == 0) {
        int b = m >> 11, s = m & 2047;
        int h = (n0 + cb) >> 6;
        __half* dst = dstH + (((size_t)(b*HH + h))*SS + s)*DHH;
        #pragma unroll
        for (int c0 = 0; c0 < 64; c0 += 8) {
            __half hv[8];
            #pragma unroll
            for (int e = 0; e < 8; ++e)
                hv[e] = __float2half((Cs[row*132 + cb + c0 + e] + bp[n0 + cb + c0 + e]) * scale);
            *(uint4*)&dst[c0] = *(uint4*)hv;
        }
    } else if (mode == 1) {
        float* dst = outF + (size_t)m*DD + n0 + cb;
        #pragma unroll
        for (int c = 0; c < 64; ++c)
            dst[c] = Cs[row*132 + cb + c] + bp[n0 + cb + c];
    } else {
        float* dst = g_hmid + (size_t)m*DHID + n0 + cb;
        #pragma unroll
        for (int c = 0; c < 64; ++c) {
            float v = Cs[row*132 + cb + c] + bp[n0 + cb + c];
            dst[c] = 0.5f * v * (1.f + erff(v * 0.70710678118654752f));
        }
    }
}

// ---------------- mech logits: dot(hmid_row, Wm2) + bm2 -----------------------
__global__ void logits_kernel(const float* __restrict__ Wm2, const float* __restrict__ bm2) {
    int m = blockIdx.x;
    int tid = threadIdx.x;           // 128
    float s = 0.f;
    for (int j = tid; j < DHID; j += 128)
        s += g_hmid[(size_t)m*DHID + j] * Wm2[j];
    #pragma unroll
    for (int o = 16; o > 0; o >>= 1) s += __shfl_xor_sync(0xffffffffu, s, o);
    __shared__ float ws[4];
    if ((tid & 31) == 0) ws[tid >> 5] = s;
    __syncthreads();
    if (tid == 0)
        g_logits[m] = ws[0] + ws[1] + ws[2] + ws[3] + bm2[0];
}

// ---------------- per-batch softmax over S=2048 -------------------------------
__global__ void mech_softmax_kernel(float* __restrict__ out_tail) {
    int b = blockIdx.x;
    int tid = threadIdx.x;           // 256
    __shared__ float red[256];
    float mx = -1e30f;
    for (int i = tid; i < SS; i += 256) mx = fmaxf(mx, g_logits[b*SS + i]);
    red[tid] = mx; __syncthreads();
    for (int s = 128; s > 0; s >>= 1) { if (tid < s) red[tid] = fmaxf(red[tid], red[tid+s]); __syncthreads(); }
    mx = red[0]; __syncthreads();
    float sm = 0.f;
    for (int i = tid; i < SS; i += 256) sm += __expf(g_logits[b*SS + i] - mx);
    red[tid] = sm; __syncthreads();
    for (int s = 128; s > 0; s >>= 1) { if (tid < s) red[tid] += red[tid+s]; __syncthreads(); }
    float inv = 1.f / red[0];
    for (int i = tid; i < SS; i += 256) {
        float v = __expf(g_logits[b*SS + i] - mx) * inv;
        g_mech[b*SS + i] = v;
        out_tail[b*SS + i] = v;
    }
}

// ---------------- attention: mma.sync, register-resident S/P/O ----------------
// 128 queries/block, 8 warps (16 q-rows each), 64-key tiles, double-buffered K/V.
// Scores are bounded -> unnormalized exp accumulation; single barrier per tile.
// smem: Qs 128x72h | Ks 2x64x72h | Vs 2x64x72h | bias 2048f  = 63488 B
__global__ void __launch_bounds__(256) attn_kernel(const int* __restrict__ mask) {
    extern __shared__ __align__(16) char dyn[];
    __half* Qs  = (__half*)dyn;              // 128*72
    __half* Ks  = Qs + 128*72;               // 2*64*72
    __half* Vs  = Ks + 2*64*72;              // 2*64*72
    float*  bias= (float*)(Vs + 2*64*72);    // 2048

    const int q0  = blockIdx.x * 128;
    const int bh  = blockIdx.y;
    const int b   = bh >> 4;
    const int h   = bh & 15;
    const int tid = threadIdx.x;
    const int w   = tid >> 5;
    const int lane= tid & 31;
    const int g   = lane >> 2;          // group row
    const int t4  = lane & 3;

    // ldmatrix per-lane address patterns
    const int arow = (lane & 7) | (((lane >> 3) & 1) << 3);   // A / V-trans pattern
    const int ac8  = lane >> 4;
    const int brow = (lane & 7) | ((lane >> 4) << 3);         // B (K) pattern
    const int bc8  = (lane >> 3) & 1;

    const __half* Qg = g_Qh + (size_t)bh * SS * DHH;
    const __half* Kg = g_Kh + (size_t)bh * SS * DHH;
    const __half* Vg = g_Vh + (size_t)bh * SS * DHH;

    // Q tile (plain vectorized copy) + bias vector
    #pragma unroll
    for (int i = 0; i < 4; ++i) {
        int idx = tid + i*256;     // 0..1023
        int r = idx >> 3, c8 = idx & 7;
        *(uint4*)(Qs + r*72 + c8*8) = *(const uint4*)(Qg + (size_t)(q0+r)*DHH + c8*8);
    }
    for (int i = tid; i < SS; i += 256)
        bias[i] = mask[b*SS + i] ? 2.0f * g_mech[b*SS + i] : -1e30f;

    #define KV_LOAD(kt, st) do {                                                  \
        const int k0_ = (kt)*64;                                                  \
        __half* ks_ = Ks + (st)*64*72;                                            \
        __half* vs_ = Vs + (st)*64*72;                                            \
        _Pragma("unroll")                                                         \
        for (int i_ = 0; i_ < 2; ++i_) {                                          \
            int idx_ = tid + i_*256;                                              \
            int r_ = idx_ >> 3, c8_ = idx_ & 7;                                   \
            cp16(ks_ + r_*72 + c8_*8, Kg + (size_t)(k0_+r_)*DHH + c8_*8);         \
            cp16(vs_ + r_*72 + c8_*8, Vg + (size_t)(k0_+r_)*DHH + c8_*8);         \
        }                                                                         \
    } while(0)

    KV_LOAD(0, 0); CP_COMMIT();
    __syncthreads();                    // Q + bias visible

    // Q fragments in registers for the whole kernel (4 k-steps of 16 d)
    uint32_t qa[4][4];
    #pragma unroll
    for (int kk = 0; kk < 4; ++kk) {
        uint32_t addr = (unsigned)__cvta_generic_to_shared(
            Qs + (w*16 + arow)*72 + kk*16 + ac8*8);
        ldm_x4(qa[kk], addr);
    }

    float oc[8][4];
    #pragma unroll
    for (int j = 0; j < 8; ++j) { oc[j][0]=0.f; oc[j][1]=0.f; oc[j][2]=0.f; oc[j][3]=0.f; }
    float rs0 = 0.f, rs1 = 0.f;

    const uint32_t KsA = (unsigned)__cvta_generic_to_shared(Ks);
    const uint32_t VsA = (unsigned)__cvta_generic_to_shared(Vs);

    for (int kt = 0; kt < 32; ++kt) {
        CP_WAIT0();
        __syncthreads();
        if (kt < 31) { KV_LOAD(kt+1, (kt+1)&1); CP_COMMIT(); }
        const uint32_t ksb = KsA + (kt&1)*64*72*2;
        const uint32_t vsb = VsA + (kt&1)*64*72*2;
        const int k0 = kt*64;

        // S = Q K^T : 16x64 in registers
        float sc[8][4];
        #pragma unroll
        for (int j = 0; j < 8; ++j) { sc[j][0]=0.f; sc[j][1]=0.f; sc[j][2]=0.f; sc[j][3]=0.f; }
        #pragma unroll
        for (int kk = 0; kk < 4; ++kk) {
            #pragma unroll
            for (int jj = 0; jj < 4; ++jj) {
                uint32_t kb[4];
                ldm_x4(kb, ksb + ((jj*16 + brow)*72 + kk*16 + bc8*8)*2);
                mma16816(sc[jj*2],   qa[kk], kb[0], kb[1]);
                mma16816(sc[jj*2+1], qa[kk], kb[2], kb[3]);
            }
        }

        // exp(S + bias) on registers; pack to half2 A-fragments
        uint32_t ph[8][2];
        #pragma unroll
        for (int j = 0; j < 8; ++j) {
            float2 bv = *(const float2*)&bias[k0 + j*8 + t4*2];
            float p0 = __expf(sc[j][0] + bv.x);
            float p1 = __expf(sc[j][1] + bv.y);
            float p2 = __expf(sc[j][2] + bv.x);
            float p3 = __expf(sc[j][3] + bv.y);
            rs0 += p0 + p1;
            rs1 += p2 + p3;
            __half2 h0 = __floats2half2_rn(p0, p1);
            __half2 h1 = __floats2half2_rn(p2, p3);
            ph[j][0] = *(uint32_t*)&h0;
            ph[j][1] = *(uint32_t*)&h1;
        }

        // O += P V
        #pragma unroll
        for (int kp = 0; kp < 4; ++kp) {
            uint32_t pa[4] = { ph[2*kp][0], ph[2*kp][1], ph[2*kp+1][0], ph[2*kp+1][1] };
            #pragma unroll
            for (int jj = 0; jj < 4; ++jj) {
                uint32_t vb[4];
                ldm_x4_t(vb, vsb + ((kp*16 + arow)*72 + jj*16 + ac8*8)*2);
                mma16816(oc[jj*2],   pa, vb[0], vb[1]);
                mma16816(oc[jj*2+1], pa, vb[2], vb[3]);
            }
        }
    }

    // row sums across the quad (lanes differing in bits 0,1 share the row)
    rs0 += __shfl_xor_sync(0xffffffffu, rs0, 1);
    rs0 += __shfl_xor_sync(0xffffffffu, rs0, 2);
    rs1 += __shfl_xor_sync(0xffffffffu, rs1, 1);
    rs1 += __shfl_xor_sync(0xffffffffu, rs1, 2);
    float inv0 = 1.f / rs0;
    float inv1 = 1.f / rs1;

    __half* d0 = g_ctxh + ((size_t)(b*SS + q0 + w*16 + g    ))*DD + h*DHH;
    __half* d1 = g_ctxh + ((size_t)(b*SS + q0 + w*16 + g + 8))*DD + h*DHH;
    #pragma unroll
    for (int j = 0; j < 8; ++j) {
        __half2 u0 = __floats2half2_rn(oc[j][0]*inv0, oc[j][1]*inv0);
        __half2 u1 = __floats2half2_rn(oc[j][2]*inv1, oc[j][3]*inv1);
        *(__half2*)&d0[j*8 + t4*2] = u0;
        *(__half2*)&d1[j*8 + t4*2] = u1;
    }
}

// ---------------- host launcher ----------------------------------------------
static void* symaddr(const void* sym) { void* p = 0; cudaGetSymbolAddress(&p, sym); return p; }

#define GEMM_SMEM 73728
#define ATTN_SMEM 63488

extern "C" void kernel_launch(void* const* d_in, const int* in_sizes, int n_in,
                              void* d_out, int out_size) {
    const float* x   = (const float*)d_in[0];
    const int*   mask= (const int*)  d_in[1];
    const float* Wq  = (const float*)d_in[2];
    const float* bq  = (const float*)d_in[3];
    const float* Wk  = (const float*)d_in[4];
    const float* bk  = (const float*)d_in[5];
    const float* Wv  = (const float*)d_in[6];
    const float* bv  = (const float*)d_in[7];
    const float* Wo  = (const float*)d_in[8];
    const float* bo  = (const float*)d_in[9];
    const float* Wm1 = (const float*)d_in[10];
    const float* bm1 = (const float*)d_in[11];
    const float* Wm2 = (const float*)d_in[12];
    const float* bm2 = (const float*)d_in[13];
    float* out = (float*)d_out;

    __half* xh   = (__half*)symaddr(g_xh);
    __half* Wqh  = (__half*)symaddr(g_Wqh);
    __half* Wkh  = (__half*)symaddr(g_Wkh);
    __half* Wvh  = (__half*)symaddr(g_Wvh);
    __half* Woh  = (__half*)symaddr(g_Woh);
    __half* Wm1h = (__half*)symaddr(g_Wm1h);
    __half* ctxh = (__half*)symaddr(g_ctxh);

    cudaFuncSetAttribute(gemm_kernel, cudaFuncAttributeMaxDynamicSharedMemorySize, GEMM_SMEM);
    cudaFuncSetAttribute(attn_kernel, cudaFuncAttributeMaxDynamicSharedMemorySize, ATTN_SMEM);

    // 1. convert inputs to fp16 (vectorized)
    f2h_kernel<<<(MM*DD/4 + 255)/256, 256>>>((const float4*)x,   (uint2*)xh,   MM*DD/4);
    f2h_kernel<<<(DD*DD/4 + 255)/256, 256>>>((const float4*)Wq,  (uint2*)Wqh,  DD*DD/4);
    f2h_kernel<<<(DD*DD/4 + 255)/256, 256>>>((const float4*)Wk,  (uint2*)Wkh,  DD*DD/4);
    f2h_kernel<<<(DD*DD/4 + 255)/256, 256>>>((const float4*)Wv,  (uint2*)Wvh,  DD*DD/4);
    f2h_kernel<<<(DD*DD/4 + 255)/256, 256>>>((const float4*)Wo,  (uint2*)Woh,  DD*DD/4);
    f2h_kernel<<<(DHID*DD/4 + 255)/256, 256>>>((const float4*)Wm1, (uint2*)Wm1h, DHID*DD/4);

    // 2. fused QKV projections (Q scaled by 1/sqrt(64))
    gemm_kernel<<<dim3(MM/128, DD/128, 3), 256, GEMM_SMEM>>>(xh, Wqh, Wkh, Wvh, bq, bk, bv, 0, 0);

    // 3. mechanism MLP layer 1 (+GELU)
    gemm_kernel<<<dim3(MM/128, DHID/128, 1), 256, GEMM_SMEM>>>(xh, Wm1h, Wm1h, Wm1h, bm1, bm1, bm1, 0, 2);

    // 4. mechanism logits + softmax (-> mech strengths, also second output)
    logits_kernel<<<MM, 128>>>(Wm2, bm2);
    mech_softmax_kernel<<<BB, 256>>>(out + (size_t)MM*DD);

    // 5. attention
    attn_kernel<<<dim3(SS/128, BB*HH), 256, ATTN_SMEM>>>(mask);

    // 6. output projection -> d_out
    gemm_kernel<<<dim3(MM/128, DD/128, 1), 256, GEMM_SMEM>>>((const __half*)ctxh, Woh, Woh, Woh, bo, bo, bo, out, 1);
}

// round 7
// speedup vs baseline: 1.9895x; 1.0307x over previous
#include <cuda_runtime.h>
#include <cuda_fp16.h>
#include <mma.h>
#include <cstdint>

using namespace nvcuda;

// Problem constants
#define BB   2
#define SS   2048
#define DD   1024
#define HH   16
#define DHH  64
#define MM   (BB*SS)          // 4096
#define DHID 512              // mech hidden

#define LOG2E 1.44269504088896340736f

// ---------------- scratch (device globals; no allocation allowed) -------------
__device__ __half g_xh  [MM*DD];
__device__ __half g_Wqh [DD*DD];
__device__ __half g_Wkh [DD*DD];
__device__ __half g_Wvh [DD*DD];
__device__ __half g_Woh [DD*DD];
__device__ __half g_Wm1h[DHID*DD];
__device__ __half g_Qh  [MM*DD];   // [b*H+h][S][64]  (Q pre-scaled by log2e/8)
__device__ __half g_Kh  [MM*DD];
__device__ __half g_Vh  [MM*DD];
__device__ __half g_ctxh[MM*DD];   // [b][s][h*64+d]
__device__ float  g_hmid[MM*DHID];
__device__ float  g_logits[MM];
__device__ float  g_mech[MM];

// ---------------- cp.async helpers -------------------------------------------
__device__ __forceinline__ void cp16(void* s, const void* g) {
    asm volatile("cp.async.ca.shared.global [%0], [%1], 16;"
                 :: "r"((unsigned)__cvta_generic_to_shared(s)), "l"(g));
}
#define CP_COMMIT() asm volatile("cp.async.commit_group;")
#define CP_WAIT0()  asm volatile("cp.async.wait_group 0;")
#define CP_WAIT1()  asm volatile("cp.async.wait_group 1;")

// ---------------- mma.sync helpers --------------------------------------------
__device__ __forceinline__ void ldm_x4(uint32_t r[4], uint32_t addr) {
    asm volatile("ldmatrix.sync.aligned.m8n8.x4.shared.b16 {%0,%1,%2,%3}, [%4];"
                 : "=r"(r[0]), "=r"(r[1]), "=r"(r[2]), "=r"(r[3]) : "r"(addr));
}
__device__ __forceinline__ void ldm_x4_t(uint32_t r[4], uint32_t addr) {
    asm volatile("ldmatrix.sync.aligned.m8n8.x4.trans.shared.b16 {%0,%1,%2,%3}, [%4];"
                 : "=r"(r[0]), "=r"(r[1]), "=r"(r[2]), "=r"(r[3]) : "r"(addr));
}
__device__ __forceinline__ void mma16816(float c[4], const uint32_t a[4], uint32_t b0, uint32_t b1) {
    asm volatile("mma.sync.aligned.m16n8k16.row.col.f32.f16.f16.f32 "
                 "{%0,%1,%2,%3}, {%4,%5,%6,%7}, {%8,%9}, {%0,%1,%2,%3};"
                 : "+f"(c[0]), "+f"(c[1]), "+f"(c[2]), "+f"(c[3])
                 : "r"(a[0]), "r"(a[1]), "r"(a[2]), "r"(a[3]), "r"(b0), "r"(b1));
}

// ---------------- fp32 -> fp16 convert (single merged launch) ------------------
#define N4_X   (MM*DD/4)                       // 1048576
#define N4_W   (DD*DD/4)                       // 262144
#define N4_WM1 (DHID*DD/4)                     // 131072
#define C0 N4_X
#define C1 (C0 + N4_W)
#define C2 (C1 + N4_W)
#define C3 (C2 + N4_W)
#define C4 (C3 + N4_W)
#define C5 (C4 + N4_WM1)
__global__ void f2h_all_kernel(
    const float4* __restrict__ x,  const float4* __restrict__ wq, const float4* __restrict__ wk,
    const float4* __restrict__ wv, const float4* __restrict__ wo, const float4* __restrict__ wm1)
{
    int i = blockIdx.x * blockDim.x + threadIdx.x;
    const float4* src; uint2* dst; int off;
    if      (i < C0) { src = x;   dst = (uint2*)g_xh;   off = i;      }
    else if (i < C1) { src = wq;  dst = (uint2*)g_Wqh;  off = i - C0; }
    else if (i < C2) { src = wk;  dst = (uint2*)g_Wkh;  off = i - C1; }
    else if (i < C3) { src = wv;  dst = (uint2*)g_Wvh;  off = i - C2; }
    else if (i < C4) { src = wo;  dst = (uint2*)g_Woh;  off = i - C3; }
    else if (i < C5) { src = wm1; dst = (uint2*)g_Wm1h; off = i - C4; }
    else return;
    float4 v = src[off];
    __half2 h0 = __floats2half2_rn(v.x, v.y);
    __half2 h1 = __floats2half2_rn(v.z, v.w);
    dst[off] = make_uint2(*(unsigned*)&h0, *(unsigned*)&h1);
}

// ---------------- 128x128-tile GEMM: C = A[M,1024] * W[N,1024]^T + b ----------
__global__ void __launch_bounds__(256) gemm_kernel(
    const __half* __restrict__ A,
    const __half* __restrict__ Wa, const __half* __restrict__ Wb, const __half* __restrict__ Wc,
    const float*  __restrict__ ba, const float*  __restrict__ bb, const float*  __restrict__ bc,
    float* __restrict__ outF, int mode)
{
    extern __shared__ __align__(16) char dyn[];
    __half* As = (__half*)dyn;           // 2 * 128*72
    __half* Bs = As + 2*128*72;          // 2 * 128*72
    float*  Cs = (float*)dyn;            // reuse: 128*132 floats

    const __half* Wp = Wa;
    const float*  bp = ba;
    __half* dstH = 0;
    float scale = 1.f;
    if (mode == 0) {
        int z = blockIdx.z;
        Wp   = (z==0) ? Wa : (z==1) ? Wb : Wc;
        bp   = (z==0) ? ba : (z==1) ? bb : bc;
        dstH = (z==0) ? g_Qh : (z==1) ? g_Kh : g_Vh;
        scale = (z==0) ? 0.125f * LOG2E : 1.f;    // fold log2e into Q for exp2 in attn
    }

    const int m0 = blockIdx.x * 128;
    const int n0 = blockIdx.y * 128;
    const int tid = threadIdx.x;
    const int wid = tid >> 5;
    const int wr  = wid & 1;       // m: 2 x 64
    const int wc  = wid >> 1;      // n: 4 x 32

    wmma::fragment<wmma::accumulator,16,16,16,float> acc[4][2];
    #pragma unroll
    for (int i = 0; i < 4; ++i) { wmma::fill_fragment(acc[i][0], 0.f); wmma::fill_fragment(acc[i][1], 0.f); }

    #define GEMM_LOAD(kt, st) do {                                                  \
        const int k0_ = (kt)*64;                                                    \
        __half* as_ = As + (st)*128*72;                                             \
        __half* bs_ = Bs + (st)*128*72;                                             \
        _Pragma("unroll")                                                           \
        for (int i_ = 0; i_ < 4; ++i_) {                                            \
            int idx_ = tid + i_*256;                                                \
            int r_ = idx_ >> 3, c8_ = idx_ & 7;                                     \
            cp16(as_ + r_*72 + c8_*8, A  + (size_t)(m0+r_)*1024 + k0_ + c8_*8);     \
            cp16(bs_ + r_*72 + c8_*8, Wp + (size_t)(n0+r_)*1024 + k0_ + c8_*8);     \
        }                                                                           \
    } while(0)

    GEMM_LOAD(0, 0); CP_COMMIT();

    for (int kt = 0; kt < 16; ++kt) {
        CP_WAIT0();
        __syncthreads();
        if (kt < 15) { GEMM_LOAD(kt+1, (kt+1)&1); CP_COMMIT(); }
        const __half* as = As + (kt&1)*128*72;
        const __half* bs = Bs + (kt&1)*128*72;
        #pragma unroll
        for (int kk = 0; kk < 4; ++kk) {
            wmma::fragment<wmma::matrix_a,16,16,16,__half,wmma::row_major> af[4];
            #pragma unroll
            for (int fm = 0; fm < 4; ++fm)
                wmma::load_matrix_sync(af[fm], as + (wr*64 + fm*16)*72 + kk*16, 72);
            #pragma unroll
            for (int fn = 0; fn < 2; ++fn) {
                wmma::fragment<wmma::matrix_b,16,16,16,__half,wmma::col_major> bf;
                wmma::load_matrix_sync(bf, bs + (wc*32 + fn*16)*72 + kk*16, 72);
                #pragma unroll
                for (int fm = 0; fm < 4; ++fm)
                    wmma::mma_sync(acc[fm][fn], af[fm], bf, acc[fm][fn]);
            }
        }
    }
    __syncthreads();

    #pragma unroll
    for (int fm = 0; fm < 4; ++fm)
        #pragma unroll
        for (int fn = 0; fn < 2; ++fn)
            wmma::store_matrix_sync(Cs + (wr*64 + fm*16)*132 + wc*32 + fn*16, acc[fm][fn], 132, wmma::mem_row_major);
    __syncthreads();

    const int row = tid >> 1;
    const int cb  = (tid & 1) * 64;
    const int m   = m0 + row;
    if (mode == 0) {
        int b = m >> 11, s = m & 2047;
        int h = (n0 + cb) >> 6;
        __half* dst = dstH + (((size_t)(b*HH + h))*SS + s)*DHH;
        #pragma unroll
        for (int c0 = 0; c0 < 64; c0 += 8) {
            __half hv[8];
            #pragma unroll
            for (int e = 0; e < 8; ++e)
                hv[e] = __float2half((Cs[row*132 + cb + c0 + e] + bp[n0 + cb + c0 + e]) * scale);
            *(uint4*)&dst[c0] = *(uint4*)hv;
        }
    } else if (mode == 1) {
        float* dst = outF + (size_t)m*DD + n0 + cb;
        #pragma unroll
        for (int c = 0; c < 64; ++c)
            dst[c] = Cs[row*132 + cb + c] + bp[n0 + cb + c];
    } else {
        float* dst = g_hmid + (size_t)m*DHID + n0 + cb;
        #pragma unroll
        for (int c = 0; c < 64; ++c) {
            float v = Cs[row*132 + cb + c] + bp[n0 + cb + c];
            dst[c] = 0.5f * v * (1.f + erff(v * 0.70710678118654752f));
        }
    }
}

// ---------------- mech logits: warp-per-row dot(hmid_row, Wm2) + bm2 ----------
__global__ void logits_kernel(const float* __restrict__ Wm2, const float* __restrict__ bm2) {
    const int w    = threadIdx.x >> 5;
    const int lane = threadIdx.x & 31;
    const int m    = blockIdx.x * 8 + w;
    const float4* hp = (const float4*)(g_hmid + (size_t)m*DHID);
    const float4* wp = (const float4*)Wm2;
    float s = 0.f;
    #pragma unroll
    for (int i = 0; i < 4; ++i) {                 // 128 float4 per row / 32 lanes
        float4 hv = hp[lane + i*32];
        float4 wv = wp[lane + i*32];
        s += hv.x*wv.x + hv.y*wv.y + hv.z*wv.z + hv.w*wv.w;
    }
    #pragma unroll
    for (int o = 16; o > 0; o >>= 1) s += __shfl_xor_sync(0xffffffffu, s, o);
    if (lane == 0) g_logits[m] = s + bm2[0];
}

// ---------------- per-batch softmax over S=2048 -------------------------------
__global__ void mech_softmax_kernel(float* __restrict__ out_tail) {
    int b = blockIdx.x;
    int tid = threadIdx.x;           // 256
    __shared__ float red[256];
    float mx = -1e30f;
    for (int i = tid; i < SS; i += 256) mx = fmaxf(mx, g_logits[b*SS + i]);
    red[tid] = mx; __syncthreads();
    for (int s = 128; s > 0; s >>= 1) { if (tid < s) red[tid] = fmaxf(red[tid], red[tid+s]); __syncthreads(); }
    mx = red[0]; __syncthreads();
    float sm = 0.f;
    for (int i = tid; i < SS; i += 256) sm += __expf(g_logits[b*SS + i] - mx);
    red[tid] = sm; __syncthreads();
    for (int s = 128; s > 0; s >>= 1) { if (tid < s) red[tid] += red[tid+s]; __syncthreads(); }
    float inv = 1.f / red[0];
    for (int i = tid; i < SS; i += 256) {
        float v = __expf(g_logits[b*SS + i] - mx) * inv;
        g_mech[b*SS + i] = v;
        out_tail[b*SS + i] = v;
    }
}

// ---------------- attention: mma.sync, register-resident S/P/O ----------------
// 128 queries/block, 8 warps (16 q-rows each), 64-key tiles, 3-stage cp.async KV ring.
// Q pre-scaled by log2e/8; bias pre-scaled by 2*log2e -> exp2f. Unnormalized accumulation.
// smem: Qs 128x72h | Ks 3x64x72h | Vs 3x64x72h | bias 2048f = 81920 B; 2 CTAs/SM.
__global__ void __launch_bounds__(256, 2) attn_kernel(const int* __restrict__ mask) {
    extern __shared__ __align__(16) char dyn[];
    __half* Qs  = (__half*)dyn;              // 128*72
    __half* Ks  = Qs + 128*72;               // 3*64*72
    __half* Vs  = Ks + 3*64*72;              // 3*64*72
    float*  bias= (float*)(Vs + 3*64*72);    // 2048

    const int q0  = blockIdx.x * 128;
    const int bh  = blockIdx.y;
    const int b   = bh >> 4;
    const int h   = bh & 15;
    const int tid = threadIdx.x;
    const int w   = tid >> 5;
    const int lane= tid & 31;
    const int g   = lane >> 2;
    const int t4  = lane & 3;

    const int arow = (lane & 7) | (((lane >> 3) & 1) << 3);
    const int ac8  = lane >> 4;
    const int brow = (lane & 7) | ((lane >> 4) << 3);
    const int bc8  = (lane >> 3) & 1;

    const __half* Qg = g_Qh + (size_t)bh * SS * DHH;
    const __half* Kg = g_Kh + (size_t)bh * SS * DHH;
    const __half* Vg = g_Vh + (size_t)bh * SS * DHH;

    #pragma unroll
    for (int i = 0; i < 4; ++i) {
        int idx = tid + i*256;
        int r = idx >> 3, c8 = idx & 7;
        *(uint4*)(Qs + r*72 + c8*8) = *(const uint4*)(Qg + (size_t)(q0+r)*DHH + c8*8);
    }
    for (int i = tid; i < SS; i += 256)
        bias[i] = mask[b*SS + i] ? (2.0f * LOG2E) * g_mech[b*SS + i] : -1e30f;

    #define KV_LOAD(kt, st) do {                                                  \
        const int k0_ = (kt)*64;                                                  \
        __half* ks_ = Ks + (st)*64*72;                                            \
        __half* vs_ = Vs + (st)*64*72;                                            \
        _Pragma("unroll")                                                         \
        for (int i_ = 0; i_ < 2; ++i_) {                                          \
            int idx_ = tid + i_*256;                                              \
            int r_ = idx_ >> 3, c8_ = idx_ & 7;                                   \
            cp16(ks_ + r_*72 + c8_*8, Kg + (size_t)(k0_+r_)*DHH + c8_*8);         \
            cp16(vs_ + r_*72 + c8_*8, Vg + (size_t)(k0_+r_)*DHH + c8_*8);         \
        }                                                                         \
    } while(0)

    KV_LOAD(0, 0); CP_COMMIT();
    KV_LOAD(1, 1); CP_COMMIT();
    __syncthreads();                 // Q + bias visible

    uint32_t qa[4][4];
    #pragma unroll
    for (int kk = 0; kk < 4; ++kk) {
        uint32_t addr = (unsigned)__cvta_generic_to_shared(
            Qs + (w*16 + arow)*72 + kk*16 + ac8*8);
        ldm_x4(qa[kk], addr);
    }

    float oc[8][4];
    #pragma unroll
    for (int j = 0; j < 8; ++j) { oc[j][0]=0.f; oc[j][1]=0.f; oc[j][2]=0.f; oc[j][3]=0.f; }
    float rs0 = 0.f, rs1 = 0.f;

    const uint32_t KsA = (unsigned)__cvta_generic_to_shared(Ks);
    const uint32_t VsA = (unsigned)__cvta_generic_to_shared(Vs);

    int st = 0;                       // stage of current tile (kt % 3)
    for (int kt = 0; kt < 32; ++kt) {
        if (kt < 31) CP_WAIT1(); else CP_WAIT0();
        __syncthreads();
        if (kt < 30) {
            int st2 = st + 2; if (st2 >= 3) st2 -= 3;
            KV_LOAD(kt+2, st2); CP_COMMIT();
        }
        const uint32_t ksb = KsA + st*64*72*2;
        const uint32_t vsb = VsA + st*64*72*2;
        const int k0 = kt*64;

        float sc[8][4];
        #pragma unroll
        for (int j = 0; j < 8; ++j) { sc[j][0]=0.f; sc[j][1]=0.f; sc[j][2]=0.f; sc[j][3]=0.f; }
        #pragma unroll
        for (int kk = 0; kk < 4; ++kk) {
            #pragma unroll
            for (int jj = 0; jj < 4; ++jj) {
                uint32_t kb[4];
                ldm_x4(kb, ksb + ((jj*16 + brow)*72 + kk*16 + bc8*8)*2);
                mma16816(sc[jj*2],   qa[kk], kb[0], kb[1]);
                mma16816(sc[jj*2+1], qa[kk], kb[2], kb[3]);
            }
        }

        uint32_t ph[8][2];
        #pragma unroll
        for (int j = 0; j < 8; ++j) {
            float2 bv = *(const float2*)&bias[k0 + j*8 + t4*2];
            float p0 = exp2f(sc[j][0] + bv.x);
            float p1 = exp2f(sc[j][1] + bv.y);
            float p2 = exp2f(sc[j][2] + bv.x);
            float p3 = exp2f(sc[j][3] + bv.y);
            rs0 += p0 + p1;
            rs1 += p2 + p3;
            __half2 h0 = __floats2half2_rn(p0, p1);
            __half2 h1 = __floats2half2_rn(p2, p3);
            ph[j][0] = *(uint32_t*)&h0;
            ph[j][1] = *(uint32_t*)&h1;
        }

        #pragma unroll
        for (int kp = 0; kp < 4; ++kp) {
            uint32_t pa[4] = { ph[2*kp][0], ph[2*kp][1], ph[2*kp+1][0], ph[2*kp+1][1] };
            #pragma unroll
            for (int jj = 0; jj < 4; ++jj) {
                uint32_t vb[4];
                ldm_x4_t(vb, vsb + ((kp*16 + arow)*72 + jj*16 + ac8*8)*2);
                mma16816(oc[jj*2],   pa, vb[0], vb[1]);
                mma16816(oc[jj*2+1], pa, vb[2], vb[3]);
            }
        }
        if (++st == 3) st = 0;
    }

    rs0 += __shfl_xor_sync(0xffffffffu, rs0, 1);
    rs0 += __shfl_xor_sync(0xffffffffu, rs0, 2);
    rs1 += __shfl_xor_sync(0xffffffffu, rs1, 1);
    rs1 += __shfl_xor_sync(0xffffffffu, rs1, 2);
    float inv0 = 1.f / rs0;
    float inv1 = 1.f / rs1;

    __half* d0 = g_ctxh + ((size_t)(b*SS + q0 + w*16 + g    ))*DD + h*DHH;
    __half* d1 = g_ctxh + ((size_t)(b*SS + q0 + w*16 + g + 8))*DD + h*DHH;
    #pragma unroll
    for (int j = 0; j < 8; ++j) {
        __half2 u0 = __floats2half2_rn(oc[j][0]*inv0, oc[j][1]*inv0);
        __half2 u1 = __floats2half2_rn(oc[j][2]*inv1, oc[j][3]*inv1);
        *(__half2*)&d0[j*8 + t4*2] = u0;
        *(__half2*)&d1[j*8 + t4*2] = u1;
    }
}

// ---------------- host launcher ----------------------------------------------
static void* symaddr(const void* sym) { void* p = 0; cudaGetSymbolAddress(&p, sym); return p; }

#define GEMM_SMEM 73728
#define ATTN_SMEM 81920

extern "C" void kernel_launch(void* const* d_in, const int* in_sizes, int n_in,
                              void* d_out, int out_size) {
    const float* x   = (const float*)d_in[0];
    const int*   mask= (const int*)  d_in[1];
    const float* Wq  = (const float*)d_in[2];
    const float* bq  = (const float*)d_in[3];
    const float* Wk  = (const float*)d_in[4];
    const float* bk  = (const float*)d_in[5];
    const float* Wv  = (const float*)d_in[6];
    const float* bv  = (const float*)d_in[7];
    const float* Wo  = (const float*)d_in[8];
    const float* bo  = (const float*)d_in[9];
    const float* Wm1 = (const float*)d_in[10];
    const float* bm1 = (const float*)d_in[11];
    const float* Wm2 = (const float*)d_in[12];
    const float* bm2 = (const float*)d_in[13];
    float* out = (float*)d_out;

    __half* xh   = (__half*)symaddr(g_xh);
    __half* Wqh  = (__half*)symaddr(g_Wqh);
    __half* Wkh  = (__half*)symaddr(g_Wkh);
    __half* Wvh  = (__half*)symaddr(g_Wvh);
    __half* Woh  = (__half*)symaddr(g_Woh);
    __half* Wm1h = (__half*)symaddr(g_Wm1h);
    __half* ctxh = (__half*)symaddr(g_ctxh);

    cudaFuncSetAttribute(gemm_kernel, cudaFuncAttributeMaxDynamicSharedMemorySize, GEMM_SMEM);
    cudaFuncSetAttribute(attn_kernel, cudaFuncAttributeMaxDynamicSharedMemorySize, ATTN_SMEM);

    // 1. convert all fp32 inputs to fp16 in one launch
    f2h_all_kernel<<<(C5 + 255)/256, 256>>>(
        (const float4*)x, (const float4*)Wq, (const float4*)Wk,
        (const float4*)Wv, (const float4*)Wo, (const float4*)Wm1);

    // 2. fused QKV projections (Q scaled by log2e/sqrt(64))
    gemm_kernel<<<dim3(MM/128, DD/128, 3), 256, GEMM_SMEM>>>(xh, Wqh, Wkh, Wvh, bq, bk, bv, 0, 0);

    // 3. mechanism MLP layer 1 (+GELU)
    gemm_kernel<<<dim3(MM/128, DHID/128, 1), 256, GEMM_SMEM>>>(xh, Wm1h, Wm1h, Wm1h, bm1, bm1, bm1, 0, 2);

    // 4. mechanism logits + softmax (-> mech strengths, also second output)
    logits_kernel<<<MM/8, 256>>>(Wm2, bm2);
    mech_softmax_kernel<<<BB, 256>>>(out + (size_t)MM*DD);

    // 5. attention
    attn_kernel<<<dim3(SS/128, BB*HH), 256, ATTN_SMEM>>>(mask);

    // 6. output projection -> d_out
    gemm_kernel<<<dim3(MM/128, DD/128, 1), 256, GEMM_SMEM>>>((const __half*)ctxh, Woh, Woh, Woh, bo, bo, bo, out, 1);
}